// round 16
// baseline (speedup 1.0000x reference)
#include <cuda_runtime.h>
#include <cuda.h>
#include <cstdint>

// ============================================================================
// Problem constants
// ============================================================================
#define NN      8192
#define DD      128

// GEMM config: dual-plane int8 mma.sync m16n8k32, both planes per CTA
// CTA tile 128x128, 16 warps (4m x 4n), warp tile 32x32, BK=128
#define BM      128
#define BN      128
#define BK      128
#define STAGES  4
#define KSPLIT  4
#define KCHUNK  (NN / KSPLIT)          // 2048
#define NKT     (KCHUNK / BK)          // 16 K iterations per CTA
#define GTHREADS 512                   // 16 warps

// SMEM: rows of 128 data bytes + 16 pad (conflict-free ldmatrix, 16B aligned)
#define RSTRIDE 144
#define A_BYTES   (BM * RSTRIDE)               // 18432
#define BP_BYTES  (BN * RSTRIDE)               // 18432 per plane
#define BH_OFF    A_BYTES
#define BL_OFF    (A_BYTES + BP_BYTES)
#define STAGE_BYTES (A_BYTES + 2 * BP_BYTES)   // 55296
#define SMEM_TOTAL  (STAGES * STAGE_BYTES)     // 221184 (1 CTA/SM)

// ============================================================================
// Scratch (device globals; allocation-free)
// ============================================================================
__device__ __align__(1024) float  g_h[NN * DD];
__device__ __align__(1024) int8_t g_A8[(size_t)NN * NN];
__device__ __align__(1024) int8_t g_hi[(size_t)DD * NN];
__device__ __align__(1024) int8_t g_lo[(size_t)DD * NN];
__device__ __align__(1024) float  g_p[KSPLIT][NN * DD];
__device__ __align__(128)  float  g_d[NN];
__device__ __align__(128)  float  g_e2[NN];          // d^2 * (1 - aii)
__device__ __align__(128)  unsigned int g_smax[DD];  // colmax |d*h| as uint bits

// ============================================================================
// PTX helpers
// ============================================================================
__device__ __forceinline__ uint32_t smem_u32(const void* p) {
    uint32_t a;
    asm("{ .reg .u64 t; cvta.to.shared.u64 t, %1; cvt.u32.u64 %0, t; }" : "=r"(a) : "l"(p));
    return a;
}

__device__ __forceinline__ void cp16(uint32_t dst, const void* src) {
    asm volatile("cp.async.cg.shared.global [%0], [%1], 16;" :: "r"(dst), "l"(src));
}

#define CP_COMMIT()  asm volatile("cp.async.commit_group;" ::: "memory")
#define CP_WAIT(n)   asm volatile("cp.async.wait_group %0;" :: "n"(n) : "memory")

// ldmatrix x4: 4 tiles of 8 rows x 16 bytes
__device__ __forceinline__ void ldsm_x4(uint32_t* r, uint32_t addr) {
    asm volatile("ldmatrix.sync.aligned.m8n8.x4.shared.b16 {%0,%1,%2,%3}, [%4];"
                 : "=r"(r[0]), "=r"(r[1]), "=r"(r[2]), "=r"(r[3]) : "r"(addr));
}

__device__ __forceinline__ void imma(int* c, const uint32_t* a, const uint32_t* b) {
    asm volatile(
        "mma.sync.aligned.m16n8k32.row.col.s32.s8.s8.s32 "
        "{%0,%1,%2,%3}, {%4,%5,%6,%7}, {%8,%9}, {%0,%1,%2,%3};"
        : "+r"(c[0]), "+r"(c[1]), "+r"(c[2]), "+r"(c[3])
        : "r"(a[0]), "r"(a[1]), "r"(a[2]), "r"(a[3]), "r"(b[0]), "r"(b[1]));
}

// evict-first float4 load (single-use stream; protects A8/hi/lo in L2)
__device__ __forceinline__ float4 ld_cs4(const float4* p) {
    float4 v;
    asm volatile("ld.global.cs.v4.f32 {%0,%1,%2,%3}, [%4];"
                 : "=f"(v.x), "=f"(v.y), "=f"(v.z), "=f"(v.w) : "l"(p));
    return v;
}

// ============================================================================
// K1 (fused): blocks 0..255 -> h = x @ W + b ; blocks 256.. -> rowsum(A) + A8
// ============================================================================
__global__ void __launch_bounds__(256) pre_kernel(const float* __restrict__ A,
                                                  const float* __restrict__ x,
                                                  const float* __restrict__ W,
                                                  const float* __restrict__ bias) {
    __shared__ float xs[32][128];
    __shared__ float red[8];
    const int tid = threadIdx.x;

    if (blockIdx.x < 256) {
        const int r0 = blockIdx.x * 32;
        const float4* xsrc = (const float4*)(x + (size_t)r0 * DD);
        float4* xdst = (float4*)&xs[0][0];
        for (int idx = tid; idx < 32 * 32; idx += 256) xdst[idx] = xsrc[idx];
        __syncthreads();

        const int n = tid & 127;
        const int rbase = (tid >> 7) * 16;
        const float b = bias[n];
        float acc[16];
#pragma unroll
        for (int r = 0; r < 16; r++) acc[r] = b;
        for (int k = 0; k < 128; k++) {
            float w = W[k * DD + n];
#pragma unroll
            for (int r = 0; r < 16; r++) acc[r] = fmaf(xs[rbase + r][k], w, acc[r]);
        }
#pragma unroll
        for (int r = 0; r < 16; r++) g_h[(size_t)(r0 + rbase + r) * DD + n] = acc[r];
    } else {
        // rowsum + int8 conversion; evict-first f32 loads, packed 16B stores.
        const int i = blockIdx.x - 256;
        const float4* row = (const float4*)(A + (size_t)i * NN);
        uint4* a8row = (uint4*)(g_A8 + (size_t)i * NN);
        float s = 0.f;
#pragma unroll
        for (int gblk = 0; gblk < 2; gblk++) {
            const int base = gblk * 1024 + tid * 4;
            float4 v[4];
#pragma unroll
            for (int j = 0; j < 4; j++) v[j] = ld_cs4(&row[base + j]);
            uint32_t pk[4];
#pragma unroll
            for (int j = 0; j < 4; j++) {
                s += (v[j].x + v[j].y) + (v[j].z + v[j].w);
                pk[j] = (uint32_t)(uint8_t)(int)v[j].x
                      | ((uint32_t)(uint8_t)(int)v[j].y << 8)
                      | ((uint32_t)(uint8_t)(int)v[j].z << 16)
                      | ((uint32_t)(uint8_t)(int)v[j].w << 24);
            }
            uint4 q;
            q.x = pk[0]; q.y = pk[1]; q.z = pk[2]; q.w = pk[3];
            a8row[gblk * 256 + tid] = q;
        }
#pragma unroll
        for (int o = 16; o; o >>= 1) s += __shfl_down_sync(0xffffffffu, s, o);
        if ((tid & 31) == 0) red[tid >> 5] = s;
        __syncthreads();
        if (tid == 0) {
            float tot = 0.f;
#pragma unroll
            for (int w = 0; w < 8; w++) tot += red[w];
            float aii = A[(size_t)i * NN + i];
            tot = tot - aii + 1.0f;
            float di = rsqrtf(tot);
            g_d[i] = di;
            g_e2[i] = di * di * (1.0f - aii);
        }
    }
}

// ============================================================================
// K2: column max |d*h| -> g_smax (atomicMax on float bits, values >= 0)
// ============================================================================
__global__ void __launch_bounds__(256) colmax_kernel() {
    __shared__ float sm[256];
    const int tid = threadIdx.x;
    const int col = tid & 127;
    const int half = tid >> 7;
    const int ibase = blockIdx.x * 64 + half * 32;
    float m = 0.f;
#pragma unroll 4
    for (int r = 0; r < 32; r++) {
        int i = ibase + r;
        float v = g_h[(size_t)i * DD + col] * g_d[i];
        m = fmaxf(m, fabsf(v));
    }
    sm[tid] = m;
    __syncthreads();
    if (tid < 128)
        atomicMax(&g_smax[col], __float_as_uint(fmaxf(sm[tid], sm[tid + 128])));
}

// ============================================================================
// K3: quantize + transpose: d*h -> hi/lo planes [n][i] int8
// ============================================================================
__global__ void __launch_bounds__(256) quant_transpose_kernel() {
    __shared__ float t[32][33];
    const int i0 = blockIdx.x * 32;
    const int n0 = blockIdx.y * 32;
    const int tx = threadIdx.x, ty = threadIdx.y;

    for (int r = ty; r < 32; r += 8) {
        int i = i0 + r;
        t[r][tx] = g_h[(size_t)i * DD + n0 + tx] * g_d[i];
    }
    __syncthreads();
    for (int r = ty; r < 32; r += 8) {
        int n = n0 + r;
        float inv = 127.f / __uint_as_float(g_smax[n]);
        float q = t[tx][r] * inv;
        float hi = rintf(q);
        hi = fminf(fmaxf(hi, -127.f), 127.f);
        float lo = rintf((q - hi) * 254.f);
        lo = fminf(fmaxf(lo, -127.f), 127.f);
        g_hi[(size_t)n * NN + i0 + tx] = (int8_t)hi;
        g_lo[(size_t)n * NN + i0 + tx] = (int8_t)lo;
    }
}

// ============================================================================
// K4: partial = fs_n * (A8 @ hi + (A8 @ lo)/254)  per K-split
//   CTA 128x128, 16 warps (4m x 4n), warp tile 32x32, BK=128,
//   4-stage cp.async pipeline, 1 CTA/SM.
// ============================================================================
__global__ void __launch_bounds__(GTHREADS, 1) gcn_gemm()
{
    extern __shared__ char smem[];
    const int tid = threadIdx.x;
    const int wid = tid >> 5;
    const int lane = tid & 31;
    const int gid = lane >> 2;
    const int tg  = lane & 3;
    const int m0 = blockIdx.x * BM;
    const int split = blockIdx.y;
    const int kbase = split * KCHUNK;
    float* __restrict__ part = g_p[split];

    const int mwb = (wid & 3) * 32;     // 4 warps along M
    const int nwb = (wid >> 2) * 32;    // 4 warps along N

    const uint32_t smem_base = smem_u32(smem);

    const int l7  = lane & 7;
    const int l8  = (lane >> 3) & 1;
    const int l16 = (lane >> 4) & 1;
    const uint32_t a_off0 = (uint32_t)((mwb + l7 + l8 * 8) * RSTRIDE + l16 * 16);
    const uint32_t a_off1 = a_off0 + 16u * RSTRIDE;
    const uint32_t b_off0 = (uint32_t)((nwb + l7 + l16 * 8) * RSTRIDE + l8 * 16);
    const uint32_t b_off1 = b_off0 + 16u * RSTRIDE;

    // -------- cp.async stage fill: 3072 x 16B (A 1024, Bhi 1024, Blo 1024) ----
    auto issue_stage = [&](int kt, int slot) {
        const int k0 = kbase + kt * BK;
        const uint32_t st = smem_base + (uint32_t)slot * STAGE_BYTES;
#pragma unroll
        for (int j = 0; j < 6; j++) {
            int c = tid + j * GTHREADS;
            int r = (c >> 3) & 127, c8 = c & 7;
            if (c < 1024) {
                cp16(st + (uint32_t)(r * RSTRIDE + c8 * 16),
                     g_A8 + (size_t)(m0 + r) * NN + k0 + c8 * 16);
            } else if (c < 2048) {
                cp16(st + BH_OFF + (uint32_t)(r * RSTRIDE + c8 * 16),
                     g_hi + (size_t)r * NN + k0 + c8 * 16);
            } else {
                cp16(st + BL_OFF + (uint32_t)(r * RSTRIDE + c8 * 16),
                     g_lo + (size_t)r * NN + k0 + c8 * 16);
            }
        }
    };

    int ch[2][4][4], cl[2][4][4];
#pragma unroll
    for (int mf = 0; mf < 2; mf++)
#pragma unroll
        for (int nf = 0; nf < 4; nf++)
#pragma unroll
            for (int q = 0; q < 4; q++) { ch[mf][nf][q] = 0; cl[mf][nf][q] = 0; }

#pragma unroll
    for (int s = 0; s < STAGES - 1; s++) {
        issue_stage(s, s);
        CP_COMMIT();
    }

    int slot_r = 0;
    int slot_w = STAGES - 1;

    for (int kt = 0; kt < NKT; kt++) {
        CP_WAIT(STAGES - 2);
        __syncthreads();

        int nxt = kt + STAGES - 1;
        if (nxt < NKT) issue_stage(nxt, slot_w);
        CP_COMMIT();
        if (++slot_w == STAGES) slot_w = 0;

        const uint32_t stg = smem_base + (uint32_t)slot_r * STAGE_BYTES;
        if (++slot_r == STAGES) slot_r = 0;

#pragma unroll
        for (int ks = 0; ks < 4; ks++) {
            const uint32_t ko = (uint32_t)ks * 32u;    // k32 step = 32 bytes
            uint32_t a0[4], a1[4], bh[8], bl[8];
            ldsm_x4(a0, stg + a_off0 + ko);
            ldsm_x4(a1, stg + a_off1 + ko);
            ldsm_x4(bh,     stg + BH_OFF + b_off0 + ko);   // nf0, nf1
            ldsm_x4(bh + 4, stg + BH_OFF + b_off1 + ko);   // nf2, nf3
            ldsm_x4(bl,     stg + BL_OFF + b_off0 + ko);
            ldsm_x4(bl + 4, stg + BL_OFF + b_off1 + ko);
#pragma unroll
            for (int nf = 0; nf < 4; nf++) {
                imma(ch[0][nf], a0, bh + nf * 2);
                imma(ch[1][nf], a1, bh + nf * 2);
                imma(cl[0][nf], a0, bl + nf * 2);
                imma(cl[1][nf], a1, bl + nf * 2);
            }
        }
    }

    // -------- epilogue: p = fs_n * (S_hi + S_lo/254), store f32 partial --------
    const float inv254 = 1.f / 254.f;
#pragma unroll
    for (int mf = 0; mf < 2; mf++) {
        int i0r = m0 + mwb + mf * 16 + gid;
        int i1r = i0r + 8;
#pragma unroll
        for (int nf = 0; nf < 4; nf++) {
            int n = nwb + nf * 8 + tg * 2;
            float fs0 = __uint_as_float(g_smax[n])     * (1.f / 127.f);
            float fs1 = __uint_as_float(g_smax[n + 1]) * (1.f / 127.f);
            float2 p0, p1;
            p0.x = fs0 * ((float)ch[mf][nf][0] + (float)cl[mf][nf][0] * inv254);
            p0.y = fs1 * ((float)ch[mf][nf][1] + (float)cl[mf][nf][1] * inv254);
            p1.x = fs0 * ((float)ch[mf][nf][2] + (float)cl[mf][nf][2] * inv254);
            p1.y = fs1 * ((float)ch[mf][nf][3] + (float)cl[mf][nf][3] * inv254);
            *(float2*)(part + (size_t)i0r * DD + n) = p0;
            *(float2*)(part + (size_t)i1r * DD + n) = p1;
        }
    }
}

// ============================================================================
// K5: out = d * sum(p[0..KSPLIT-1]) + e2 * h    (e2 = d^2 (1-aii))
// ============================================================================
__global__ void __launch_bounds__(256) combine_kernel(float* __restrict__ out) {
    const int idx = blockIdx.x * 256 + threadIdx.x;      // float4 index
    const int i = (idx * 4) / DD;
    const float d = g_d[i], e2 = g_e2[i];
    float4 s = ((const float4*)g_p[0])[idx];
#pragma unroll
    for (int p = 1; p < KSPLIT; p++) {
        const float4 v = ((const float4*)g_p[p])[idx];
        s.x += v.x; s.y += v.y; s.z += v.z; s.w += v.w;
    }
    const float4 hv = ((const float4*)g_h)[idx];
    float4 o;
    o.x = d * s.x + e2 * hv.x;
    o.y = d * s.y + e2 * hv.y;
    o.z = d * s.z + e2 * hv.z;
    o.w = d * s.w + e2 * hv.w;
    ((float4*)out)[idx] = o;
}

// ============================================================================
// Host side
// ============================================================================
extern "C" void kernel_launch(void* const* d_in, const int* in_sizes, int n_in,
                              void* d_out, int out_size) {
    const float* A    = (const float*)d_in[0];
    const float* x    = (const float*)d_in[1];
    const float* W    = (const float*)d_in[2];
    const float* bias = (const float*)d_in[3];
    float* out = (float*)d_out;

    cudaFuncSetAttribute(gcn_gemm, cudaFuncAttributeMaxDynamicSharedMemorySize, SMEM_TOTAL);

    pre_kernel<<<NN + 256, 256>>>(A, x, W, bias);
    colmax_kernel<<<NN / 64, 256>>>();
    quant_transpose_kernel<<<dim3(NN / 32, DD / 32), dim3(32, 8)>>>();
    gcn_gemm<<<dim3(NN / BM, KSPLIT), GTHREADS, SMEM_TOTAL>>>();
    combine_kernel<<<(NN * DD / 4) / 256, 256>>>(out);
}